// round 2
// baseline (speedup 1.0000x reference)
#include <cuda_runtime.h>
#include <math.h>
#include <stdint.h>

#define NTOK 1024
#define CQ   768
#define CZ   128
#define NH   16
#define DH   48
#define HD   768
#define EPSV 1e-5f
#define INFV 1.0e9f

// ------------- static device scratch (no allocations allowed) -------------
__device__ float g_an[NTOK * CQ];
__device__ float g_q [NTOK * HD];
__device__ float g_k [NTOK * HD];
__device__ float g_v [NTOK * HD];
__device__ float g_g [NTOK * HD];
__device__ float g_og[NTOK * HD];
__device__ float g_bias[(size_t)NH * NTOK * NTOK];   // [h][i][j] 64 MB

// ===========================================================================
// Kernel 1: LayerNorm(a) -> g_an.   1024 blocks x 256 threads.
// ===========================================================================
__global__ __launch_bounds__(256) void ln_a_kernel(const float* __restrict__ a,
                                                   const float* __restrict__ ga,
                                                   const float* __restrict__ ba)
{
    int row = blockIdx.x;
    int tid = threadIdx.x;
    const float* x = a + row * CQ;
    float v0 = x[tid], v1 = x[tid + 256], v2 = x[tid + 512];
    float s = v0 + v1 + v2;
    float q = v0 * v0 + v1 * v1 + v2 * v2;
#pragma unroll
    for (int o = 16; o > 0; o >>= 1) {
        s += __shfl_xor_sync(0xffffffffu, s, o);
        q += __shfl_xor_sync(0xffffffffu, q, o);
    }
    __shared__ float sw[8], qw[8];
    __shared__ float smu, srv;
    if ((tid & 31) == 0) { sw[tid >> 5] = s; qw[tid >> 5] = q; }
    __syncthreads();
    if (tid == 0) {
        float S = 0.f, Q = 0.f;
#pragma unroll
        for (int w = 0; w < 8; w++) { S += sw[w]; Q += qw[w]; }
        float mu = S * (1.f / (float)CQ);
        float var = Q * (1.f / (float)CQ) - mu * mu;
        smu = mu;
        srv = rsqrtf(fmaxf(var, 0.f) + EPSV);
    }
    __syncthreads();
    float mu = smu, r = srv;
    float* o = g_an + row * CQ;
    o[tid]       = (v0 - mu) * r * ga[tid]       + ba[tid];
    o[tid + 256] = (v1 - mu) * r * ga[tid + 256] + ba[tid + 256];
    o[tid + 512] = (v2 - mu) * r * ga[tid + 512] + ba[tid + 512];
}

// ===========================================================================
// Kernel 2: fused QKVG projections.  an[1024,768] @ W[768,768] for 4 weights.
// BM=128, BN=128, BK=16, 256 threads, 8x8 microtile. grid (24, 8).
// sel 0: q (scaled by 1/sqrt(48)), 1: k, 2: v, 3: gate = sigmoid(x + b_g).
// ===========================================================================
__global__ __launch_bounds__(256, 2) void proj_kernel(const float* __restrict__ Wq,
                                                      const float* __restrict__ Wk,
                                                      const float* __restrict__ Wv,
                                                      const float* __restrict__ Wg,
                                                      const float* __restrict__ bg)
{
    const int BM = 128, BN = 128, BK = 16;
    int bn = blockIdx.x;                 // 0..23
    int bm = blockIdx.y;                 // 0..7
    int n0 = bn * BN;
    int sel  = n0 / HD;                  // tile never straddles weight boundary
    int ncol = n0 - sel * HD;
    const float* W = (sel == 0) ? Wq : (sel == 1) ? Wk : (sel == 2) ? Wv : Wg;
    float*       O = (sel == 0) ? g_q : (sel == 1) ? g_k : (sel == 2) ? g_v : g_g;

    __shared__ __align__(16) float As[BK][BM];
    __shared__ __align__(16) float Bs[BK][BN];
    int tid = threadIdx.x;
    int tx = tid & 15, ty = tid >> 4;
    int m0 = bm * BM;

    float acc[8][8];
#pragma unroll
    for (int i = 0; i < 8; i++)
#pragma unroll
        for (int j = 0; j < 8; j++) acc[i][j] = 0.f;

    for (int k0 = 0; k0 < CQ; k0 += BK) {
#pragma unroll
        for (int t = 0; t < 2; t++) {
            int f = tid + t * 256;
            int m = f >> 2, kq = (f & 3) * 4;
            float4 av = *(const float4*)&g_an[(m0 + m) * CQ + k0 + kq];
            As[kq + 0][m] = av.x; As[kq + 1][m] = av.y;
            As[kq + 2][m] = av.z; As[kq + 3][m] = av.w;
        }
#pragma unroll
        for (int t = 0; t < 2; t++) {
            int f = tid + t * 256;
            int r = f >> 5, c = (f & 31) * 4;
            *(float4*)&Bs[r][c] = *(const float4*)&W[(k0 + r) * HD + ncol + c];
        }
        __syncthreads();
#pragma unroll
        for (int k = 0; k < BK; k++) {
            float a[8], b[8];
            *(float4*)(a)     = *(const float4*)&As[k][ty * 8];
            *(float4*)(a + 4) = *(const float4*)&As[k][ty * 8 + 4];
            *(float4*)(b)     = *(const float4*)&Bs[k][tx * 8];
            *(float4*)(b + 4) = *(const float4*)&Bs[k][tx * 8 + 4];
#pragma unroll
            for (int i = 0; i < 8; i++)
#pragma unroll
                for (int j = 0; j < 8; j++)
                    acc[i][j] = fmaf(a[i], b[j], acc[i][j]);
        }
        __syncthreads();
    }

    const float scaleq = 0.14433756729740643f;   // 1/sqrt(48)
#pragma unroll
    for (int i = 0; i < 8; i++) {
        int m = m0 + ty * 8 + i;
#pragma unroll
        for (int j0 = 0; j0 < 8; j0 += 4) {
            float v[4];
#pragma unroll
            for (int u = 0; u < 4; u++) {
                float val = acc[i][j0 + u];
                int c = ncol + tx * 8 + j0 + u;
                if (sel == 0) val *= scaleq;
                else if (sel == 3) val = 1.f / (1.f + __expf(-(val + bg[c])));
                v[u] = val;
            }
            float4 o4; o4.x = v[0]; o4.y = v[1]; o4.z = v[2]; o4.w = v[3];
            *(float4*)&O[m * HD + ncol + tx * 8 + j0] = o4;
        }
    }
}

// ===========================================================================
// Kernel 3: pair bias with fused LayerNorm (algebraic).
//   bias[h][i][j] = r_ij*(dot(z_ij, wg_h) - mu_ij*S_h) + Bc_h
//   wg = g_z .* w_z,  S_h = sum_c wg,  Bc_h = sum_c b_z*w_z
// Grid (16 j-tiles, 1024 i). 64 threads, 4h x 4j microtile.
// ===========================================================================
__global__ __launch_bounds__(64) void pairbias_kernel(const float* __restrict__ z,
                                                      const float* __restrict__ gz,
                                                      const float* __restrict__ bz,
                                                      const float* __restrict__ wz)
{
    __shared__ float zs[64][CZ + 1];             // stride 129 -> bank-clean
    __shared__ __align__(16) float wgs[CZ][NH];
    __shared__ float Ssh[NH], Bcsh[NH];
    __shared__ float mus[64], rvs[64];
    int tid = threadIdx.x;
    int i = blockIdx.y;
    int j0 = blockIdx.x * 64;

    for (int t = tid; t < CZ * NH; t += 64) {
        int c = t >> 4, h = t & 15;
        wgs[c][h] = gz[c] * wz[c * NH + h];
    }
    const float* zbase = z + ((size_t)i * NTOK + j0) * CZ;
    for (int t = tid; t < 64 * (CZ / 4); t += 64) {
        int r = t >> 5, c4 = (t & 31) * 4;
        float4 v = *(const float4*)(zbase + r * CZ + c4);
        zs[r][c4] = v.x; zs[r][c4 + 1] = v.y; zs[r][c4 + 2] = v.z; zs[r][c4 + 3] = v.w;
    }
    __syncthreads();
    if (tid < NH) {
        float S = 0.f, Bc = 0.f;
        for (int c = 0; c < CZ; c++) { S += wgs[c][tid]; Bc += bz[c] * wz[c * NH + tid]; }
        Ssh[tid] = S; Bcsh[tid] = Bc;
    }
    {   // per-row stats: one thread per j row
        float s = 0.f, sq = 0.f;
        for (int c = 0; c < CZ; c++) { float v = zs[tid][c]; s += v; sq = fmaf(v, v, sq); }
        float mu = s * (1.f / (float)CZ);
        mus[tid] = mu;
        rvs[tid] = rsqrtf(fmaxf(sq * (1.f / (float)CZ) - mu * mu, 0.f) + EPSV);
    }
    __syncthreads();

    int tx = tid & 3, ty = tid >> 2;     // tx: head quad, ty: j quad
    int h0 = tx * 4, r0 = ty * 4;
    float acc[4][4];
#pragma unroll
    for (int u = 0; u < 4; u++)
#pragma unroll
        for (int w = 0; w < 4; w++) acc[u][w] = 0.f;

#pragma unroll 4
    for (int c = 0; c < CZ; c++) {
        float4 w4 = *(const float4*)&wgs[c][h0];
        float zz[4];
#pragma unroll
        for (int u = 0; u < 4; u++) zz[u] = zs[r0 + u][c];
#pragma unroll
        for (int u = 0; u < 4; u++) {
            acc[u][0] = fmaf(zz[u], w4.x, acc[u][0]);
            acc[u][1] = fmaf(zz[u], w4.y, acc[u][1]);
            acc[u][2] = fmaf(zz[u], w4.z, acc[u][2]);
            acc[u][3] = fmaf(zz[u], w4.w, acc[u][3]);
        }
    }
#pragma unroll
    for (int w = 0; w < 4; w++) {
        int h = h0 + w;
        float S = Ssh[h], Bc = Bcsh[h];
        float* out = g_bias + ((size_t)h * NTOK + i) * NTOK + j0 + r0;
        float4 o4;
        o4.x = rvs[r0 + 0] * (acc[0][w] - mus[r0 + 0] * S) + Bc;
        o4.y = rvs[r0 + 1] * (acc[1][w] - mus[r0 + 1] * S) + Bc;
        o4.z = rvs[r0 + 2] * (acc[2][w] - mus[r0 + 2] * S) + Bc;
        o4.w = rvs[r0 + 3] * (acc[3][w] - mus[r0 + 3] * S) + Bc;
        *(float4*)out = o4;
    }
}

// ===========================================================================
// Kernel 4: flash attention with bias + gating.
// Block = (64-query tile, 1 head). 256 threads: tx 0..15, ty 0..15.
// Scores: 4q x 4j microtile, K transposed in smem. PV: 4q x 3d.
// Epilogue multiplies by the sigmoid gate and writes g_og.
// ===========================================================================
__global__ __launch_bounds__(256) void attn_kernel(const float* __restrict__ mask)
{
    int h  = blockIdx.y;
    int q0 = blockIdx.x * 64;
    int tid = threadIdx.x;
    int tx = tid & 15, ty = tid >> 4;

    __shared__ __align__(16) float qs[64][52];
    __shared__ __align__(16) float kv[64 * 52];     // union: ks_t[48][68] / vs[64][52]
    __shared__ __align__(16) float ps[64][68];

    for (int t = tid; t < 64 * 12; t += 256) {
        int r = t / 12, c4 = (t % 12) * 4;
        float4 v = *(const float4*)&g_q[(q0 + r) * HD + h * DH + c4];
        qs[r][c4] = v.x; qs[r][c4 + 1] = v.y; qs[r][c4 + 2] = v.z; qs[r][c4 + 3] = v.w;
    }

    float mrow[4], lrow[4], o[4][3];
#pragma unroll
    for (int i = 0; i < 4; i++) {
        mrow[i] = -1e30f; lrow[i] = 0.f;
        o[i][0] = o[i][1] = o[i][2] = 0.f;
    }
    float mq[4];
#pragma unroll
    for (int i = 0; i < 4; i++) mq[i] = mask[q0 + ty * 4 + i];

    for (int jt = 0; jt < 16; jt++) {
        int j0 = jt * 64;
        __syncthreads();                      // prev-iter v reads done
        // K transposed: ks_t[d][j]
        for (int t = tid; t < 64 * 12; t += 256) {
            int j = t & 63, d4 = (t >> 6) * 4;
            float4 v = *(const float4*)&g_k[(j0 + j) * HD + h * DH + d4];
            kv[(d4 + 0) * 68 + j] = v.x;
            kv[(d4 + 1) * 68 + j] = v.y;
            kv[(d4 + 2) * 68 + j] = v.z;
            kv[(d4 + 3) * 68 + j] = v.w;
        }
        __syncthreads();

        float s[4][4];
#pragma unroll
        for (int i = 0; i < 4; i++)
#pragma unroll
            for (int u = 0; u < 4; u++) s[i][u] = 0.f;
#pragma unroll 4
        for (int d = 0; d < DH; d++) {
            float4 b4 = *(float4*)&kv[d * 68 + tx * 4];
#pragma unroll
            for (int i = 0; i < 4; i++) {
                float a = qs[ty * 4 + i][d];
                s[i][0] = fmaf(a, b4.x, s[i][0]);
                s[i][1] = fmaf(a, b4.y, s[i][1]);
                s[i][2] = fmaf(a, b4.z, s[i][2]);
                s[i][3] = fmaf(a, b4.w, s[i][3]);
            }
        }
        float mk[4];
#pragma unroll
        for (int u = 0; u < 4; u++) mk[u] = mask[j0 + tx * 4 + u];
#pragma unroll
        for (int i = 0; i < 4; i++) {
            const float* bp = g_bias + ((size_t)h * NTOK + q0 + ty * 4 + i) * NTOK + j0 + tx * 4;
            float4 b4 = *(const float4*)bp;
            s[i][0] += b4.x + INFV * (mq[i] * mk[0] - 1.f);
            s[i][1] += b4.y + INFV * (mq[i] * mk[1] - 1.f);
            s[i][2] += b4.z + INFV * (mq[i] * mk[2] - 1.f);
            s[i][3] += b4.w + INFV * (mq[i] * mk[3] - 1.f);
        }
        // online softmax; row state replicated across the 16 tx lanes
#pragma unroll
        for (int i = 0; i < 4; i++) {
            float mx = fmaxf(fmaxf(s[i][0], s[i][1]), fmaxf(s[i][2], s[i][3]));
#pragma unroll
            for (int off = 1; off < 16; off <<= 1)
                mx = fmaxf(mx, __shfl_xor_sync(0xffffffffu, mx, off));
            float mnew = fmaxf(mrow[i], mx);
            float scale = __expf(mrow[i] - mnew);
            float psum = 0.f;
#pragma unroll
            for (int u = 0; u < 4; u++) { s[i][u] = __expf(s[i][u] - mnew); psum += s[i][u]; }
#pragma unroll
            for (int off = 1; off < 16; off <<= 1)
                psum += __shfl_xor_sync(0xffffffffu, psum, off);
            lrow[i] = lrow[i] * scale + psum;
            mrow[i] = mnew;
            o[i][0] *= scale; o[i][1] *= scale; o[i][2] *= scale;
            *(float4*)&ps[ty * 4 + i][tx * 4] = make_float4(s[i][0], s[i][1], s[i][2], s[i][3]);
        }
        __syncthreads();                      // k reads done, ps visible
        // V natural layout
        for (int t = tid; t < 64 * 12; t += 256) {
            int r = t / 12, c4 = (t % 12) * 4;
            float4 v = *(const float4*)&g_v[(j0 + r) * HD + h * DH + c4];
            kv[r * 52 + c4] = v.x; kv[r * 52 + c4 + 1] = v.y;
            kv[r * 52 + c4 + 2] = v.z; kv[r * 52 + c4 + 3] = v.w;
        }
        __syncthreads();
        int d0 = tx * 3;
#pragma unroll 4
        for (int j = 0; j < 64; j++) {
            float b0 = kv[j * 52 + d0], b1 = kv[j * 52 + d0 + 1], b2 = kv[j * 52 + d0 + 2];
#pragma unroll
            for (int i = 0; i < 4; i++) {
                float p = ps[ty * 4 + i][j];
                o[i][0] = fmaf(p, b0, o[i][0]);
                o[i][1] = fmaf(p, b1, o[i][1]);
                o[i][2] = fmaf(p, b2, o[i][2]);
            }
        }
    }
#pragma unroll
    for (int i = 0; i < 4; i++) {
        int q = q0 + ty * 4 + i;
        float inv = 1.f / lrow[i];
        int base = q * HD + h * DH + tx * 3;
#pragma unroll
        for (int u = 0; u < 3; u++)
            g_og[base + u] = o[i][u] * inv * g_g[base + u];
    }
}

// ===========================================================================
// Kernel 5: output projection.  og[1024,768] @ w_o[768,768] + b_o -> out.
// Same tiling as proj. grid (6, 8).
// ===========================================================================
__global__ __launch_bounds__(256, 2) void outproj_kernel(const float* __restrict__ W,
                                                         const float* __restrict__ bo,
                                                         float* __restrict__ out)
{
    const int BM = 128, BN = 128, BK = 16;
    int n0 = blockIdx.x * BN;
    int m0 = blockIdx.y * BM;

    __shared__ __align__(16) float As[BK][BM];
    __shared__ __align__(16) float Bs[BK][BN];
    int tid = threadIdx.x;
    int tx = tid & 15, ty = tid >> 4;

    float acc[8][8];
#pragma unroll
    for (int i = 0; i < 8; i++)
#pragma unroll
        for (int j = 0; j < 8; j++) acc[i][j] = 0.f;

    for (int k0 = 0; k0 < HD; k0 += BK) {
#pragma unroll
        for (int t = 0; t < 2; t++) {
            int f = tid + t * 256;
            int m = f >> 2, kq = (f & 3) * 4;
            float4 av = *(const float4*)&g_og[(m0 + m) * HD + k0 + kq];
            As[kq + 0][m] = av.x; As[kq + 1][m] = av.y;
            As[kq + 2][m] = av.z; As[kq + 3][m] = av.w;
        }
#pragma unroll
        for (int t = 0; t < 2; t++) {
            int f = tid + t * 256;
            int r = f >> 5, c = (f & 31) * 4;
            *(float4*)&Bs[r][c] = *(const float4*)&W[(k0 + r) * CQ + n0 + c];
        }
        __syncthreads();
#pragma unroll
        for (int k = 0; k < BK; k++) {
            float a[8], b[8];
            *(float4*)(a)     = *(const float4*)&As[k][ty * 8];
            *(float4*)(a + 4) = *(const float4*)&As[k][ty * 8 + 4];
            *(float4*)(b)     = *(const float4*)&Bs[k][tx * 8];
            *(float4*)(b + 4) = *(const float4*)&Bs[k][tx * 8 + 4];
#pragma unroll
            for (int i = 0; i < 8; i++)
#pragma unroll
                for (int j = 0; j < 8; j++)
                    acc[i][j] = fmaf(a[i], b[j], acc[i][j]);
        }
        __syncthreads();
    }
#pragma unroll
    for (int i = 0; i < 8; i++) {
        int m = m0 + ty * 8 + i;
#pragma unroll
        for (int j0 = 0; j0 < 8; j0 += 4) {
            int c = n0 + tx * 8 + j0;
            float4 o4;
            o4.x = acc[i][j0 + 0] + bo[c + 0];
            o4.y = acc[i][j0 + 1] + bo[c + 1];
            o4.z = acc[i][j0 + 2] + bo[c + 2];
            o4.w = acc[i][j0 + 3] + bo[c + 3];
            *(float4*)&out[m * CQ + c] = o4;
        }
    }
}

// ===========================================================================
extern "C" void kernel_launch(void* const* d_in, const int* in_sizes, int n_in,
                              void* d_out, int out_size)
{
    const float* a    = (const float*)d_in[0];
    const float* z    = (const float*)d_in[1];
    const float* mask = (const float*)d_in[2];
    const float* g_a  = (const float*)d_in[3];
    const float* b_a  = (const float*)d_in[4];
    const float* g_z  = (const float*)d_in[5];
    const float* b_z  = (const float*)d_in[6];
    const float* w_z  = (const float*)d_in[7];
    const float* w_q  = (const float*)d_in[8];
    const float* w_k  = (const float*)d_in[9];
    const float* w_v  = (const float*)d_in[10];
    const float* w_g  = (const float*)d_in[11];
    const float* b_g  = (const float*)d_in[12];
    const float* w_o  = (const float*)d_in[13];
    const float* b_o  = (const float*)d_in[14];
    float* out = (float*)d_out;

    ln_a_kernel<<<NTOK, 256>>>(a, g_a, b_a);
    proj_kernel<<<dim3(24, 8), 256>>>(w_q, w_k, w_v, w_g, b_g);
    pairbias_kernel<<<dim3(16, NTOK), 64>>>(z, g_z, b_z, w_z);
    attn_kernel<<<dim3(16, NH), 256>>>(mask);
    outproj_kernel<<<dim3(6, 8), 256>>>(w_o, b_o, out);
}

// round 3
// speedup vs baseline: 1.1149x; 1.1149x over previous
#include <cuda_runtime.h>
#include <math.h>
#include <stdint.h>

#define NTOK 1024
#define CQ   768
#define CZ   128
#define NH   16
#define DH   48
#define HD   768
#define EPSV 1e-5f
#define INFV 1.0e9f

// ------------- static device scratch (no allocations allowed) -------------
__device__ float g_an[NTOK * CQ];
__device__ float g_q [NTOK * HD];
__device__ float g_k [NTOK * HD];
__device__ float g_v [NTOK * HD];
__device__ float g_g [NTOK * HD];
__device__ float g_og[NTOK * HD];
__device__ float g_bias[(size_t)NH * NTOK * NTOK];   // [h][i][j] 64 MB

// ===========================================================================
// Kernel 1: LayerNorm(a) -> g_an.   1024 blocks x 256 threads.
// ===========================================================================
__global__ __launch_bounds__(256) void ln_a_kernel(const float* __restrict__ a,
                                                   const float* __restrict__ ga,
                                                   const float* __restrict__ ba)
{
    int row = blockIdx.x;
    int tid = threadIdx.x;
    const float* x = a + row * CQ;
    float v0 = x[tid], v1 = x[tid + 256], v2 = x[tid + 512];
    float s = v0 + v1 + v2;
    float q = v0 * v0 + v1 * v1 + v2 * v2;
#pragma unroll
    for (int o = 16; o > 0; o >>= 1) {
        s += __shfl_xor_sync(0xffffffffu, s, o);
        q += __shfl_xor_sync(0xffffffffu, q, o);
    }
    __shared__ float sw[8], qw[8];
    __shared__ float smu, srv;
    if ((tid & 31) == 0) { sw[tid >> 5] = s; qw[tid >> 5] = q; }
    __syncthreads();
    if (tid == 0) {
        float S = 0.f, Q = 0.f;
#pragma unroll
        for (int w = 0; w < 8; w++) { S += sw[w]; Q += qw[w]; }
        float mu = S * (1.f / (float)CQ);
        float var = Q * (1.f / (float)CQ) - mu * mu;
        smu = mu;
        srv = rsqrtf(fmaxf(var, 0.f) + EPSV);
    }
    __syncthreads();
    float mu = smu, r = srv;
    float* o = g_an + row * CQ;
    o[tid]       = (v0 - mu) * r * ga[tid]       + ba[tid];
    o[tid + 256] = (v1 - mu) * r * ga[tid + 256] + ba[tid + 256];
    o[tid + 512] = (v2 - mu) * r * ga[tid + 512] + ba[tid + 512];
}

// ===========================================================================
// Kernel 2: fused QKVG projections. BM=128, BN=128, BK=16, 8x8 microtile.
// grid (24, 8), 256 threads. As stride padded 128->132 (STS conflict 4x->2x).
// ===========================================================================
__global__ __launch_bounds__(256, 2) void proj_kernel(const float* __restrict__ Wq,
                                                      const float* __restrict__ Wk,
                                                      const float* __restrict__ Wv,
                                                      const float* __restrict__ Wg,
                                                      const float* __restrict__ bg)
{
    const int BK = 16, BN = 128;
    int n0 = blockIdx.x * BN;
    int sel  = n0 / HD;
    int ncol = n0 - sel * HD;
    const float* W = (sel == 0) ? Wq : (sel == 1) ? Wk : (sel == 2) ? Wv : Wg;
    float*       O = (sel == 0) ? g_q : (sel == 1) ? g_k : (sel == 2) ? g_v : g_g;

    __shared__ __align__(16) float As[BK][132];
    __shared__ __align__(16) float Bs[BK][BN];
    int tid = threadIdx.x;
    int tx = tid & 15, ty = tid >> 4;
    int m0 = blockIdx.y * 128;

    float acc[8][8];
#pragma unroll
    for (int i = 0; i < 8; i++)
#pragma unroll
        for (int j = 0; j < 8; j++) acc[i][j] = 0.f;

    for (int k0 = 0; k0 < CQ; k0 += BK) {
#pragma unroll
        for (int t = 0; t < 2; t++) {
            int f = tid + t * 256;
            int m = f >> 2, kq = (f & 3) * 4;
            float4 av = *(const float4*)&g_an[(m0 + m) * CQ + k0 + kq];
            As[kq + 0][m] = av.x; As[kq + 1][m] = av.y;
            As[kq + 2][m] = av.z; As[kq + 3][m] = av.w;
        }
#pragma unroll
        for (int t = 0; t < 2; t++) {
            int f = tid + t * 256;
            int r = f >> 5, c = (f & 31) * 4;
            *(float4*)&Bs[r][c] = *(const float4*)&W[(k0 + r) * HD + ncol + c];
        }
        __syncthreads();
#pragma unroll
        for (int k = 0; k < BK; k++) {
            float a[8], b[8];
            *(float4*)(a)     = *(const float4*)&As[k][ty * 8];
            *(float4*)(a + 4) = *(const float4*)&As[k][ty * 8 + 4];
            *(float4*)(b)     = *(const float4*)&Bs[k][tx * 8];
            *(float4*)(b + 4) = *(const float4*)&Bs[k][tx * 8 + 4];
#pragma unroll
            for (int i = 0; i < 8; i++)
#pragma unroll
                for (int j = 0; j < 8; j++)
                    acc[i][j] = fmaf(a[i], b[j], acc[i][j]);
        }
        __syncthreads();
    }

    const float scaleq = 0.14433756729740643f;   // 1/sqrt(48)
#pragma unroll
    for (int i = 0; i < 8; i++) {
        int m = m0 + ty * 8 + i;
#pragma unroll
        for (int j0 = 0; j0 < 8; j0 += 4) {
            float v[4];
#pragma unroll
            for (int u = 0; u < 4; u++) {
                float val = acc[i][j0 + u];
                int c = ncol + tx * 8 + j0 + u;
                if (sel == 0) val *= scaleq;
                else if (sel == 3) val = 1.f / (1.f + __expf(-(val + bg[c])));
                v[u] = val;
            }
            float4 o4; o4.x = v[0]; o4.y = v[1]; o4.z = v[2]; o4.w = v[3];
            *(float4*)&O[m * HD + ncol + tx * 8 + j0] = o4;
        }
    }
}

// ===========================================================================
// Kernel 3: pair bias with fused LayerNorm (algebraic).
//   bias[h][i][j] = r_ij*(dot(z_ij, wg_h) - mu_ij*S_h) + Bc_h
// z staged in smem as float4-blocked [cq][row], stride 65 (conflict-free).
// 64 threads; microtile 4h (tx*4) x 4j (rows ty + 16u). 8 LDS.128 / 64 FMA.
// Grid (16 j-tiles, 1024 i).
// ===========================================================================
__global__ __launch_bounds__(64) void pairbias_kernel(const float* __restrict__ z,
                                                      const float* __restrict__ gz,
                                                      const float* __restrict__ bz,
                                                      const float* __restrict__ wz)
{
    __shared__ __align__(16) float4 zs4[32 * 65];      // z[row][4cq..4cq+3]
    __shared__ __align__(16) float wgs[CZ][NH];
    __shared__ float Ssh[NH], Bcsh[NH], mus[64], rvs[64];
    int tid = threadIdx.x;
    int i = blockIdx.y;
    int j0 = blockIdx.x * 64;

    for (int t = tid; t < CZ * NH; t += 64) {
        int c = t >> 4, h = t & 15;
        wgs[c][h] = gz[c] * wz[c * NH + h];
    }
    const float4* zb4 = (const float4*)(z + ((size_t)i * NTOK + j0) * CZ);
    for (int t = tid; t < 2048; t += 64) {
        int r = t >> 5, cq = t & 31;
        zs4[cq * 65 + r] = zb4[r * 32 + cq];
    }
    __syncthreads();
    if (tid < NH) {
        float S = 0.f, Bc = 0.f;
        for (int c = 0; c < CZ; c++) { S += wgs[c][tid]; Bc += bz[c] * wz[c * NH + tid]; }
        Ssh[tid] = S; Bcsh[tid] = Bc;
    }
    {   // per-row stats: one thread per j row
        float s = 0.f, sq = 0.f;
        for (int cq = 0; cq < 32; cq++) {
            float4 v = zs4[cq * 65 + tid];
            s += v.x + v.y + v.z + v.w;
            sq = fmaf(v.x, v.x, sq); sq = fmaf(v.y, v.y, sq);
            sq = fmaf(v.z, v.z, sq); sq = fmaf(v.w, v.w, sq);
        }
        float mu = s * (1.f / (float)CZ);
        mus[tid] = mu;
        rvs[tid] = rsqrtf(fmaxf(sq * (1.f / (float)CZ) - mu * mu, 0.f) + EPSV);
    }
    __syncthreads();

    int tx = tid & 3, ty = tid >> 2;     // tx: head quad, ty: base row (0..15)
    int h0 = tx * 4;
    float acc[4][4];                     // [row u][head w]
#pragma unroll
    for (int u = 0; u < 4; u++)
#pragma unroll
        for (int w = 0; w < 4; w++) acc[u][w] = 0.f;

    for (int cq = 0; cq < 32; cq++) {
        float za[4][4];
        *(float4*)za[0] = zs4[cq * 65 + ty];
        *(float4*)za[1] = zs4[cq * 65 + ty + 16];
        *(float4*)za[2] = zs4[cq * 65 + ty + 32];
        *(float4*)za[3] = zs4[cq * 65 + ty + 48];
#pragma unroll
        for (int k = 0; k < 4; k++) {
            float4 w4 = *(const float4*)&wgs[cq * 4 + k][h0];
#pragma unroll
            for (int u = 0; u < 4; u++) {
                acc[u][0] = fmaf(za[u][k], w4.x, acc[u][0]);
                acc[u][1] = fmaf(za[u][k], w4.y, acc[u][1]);
                acc[u][2] = fmaf(za[u][k], w4.z, acc[u][2]);
                acc[u][3] = fmaf(za[u][k], w4.w, acc[u][3]);
            }
        }
    }
#pragma unroll
    for (int u = 0; u < 4; u++) {
        int r = ty + 16 * u;
        float mu = mus[r], rv = rvs[r];
#pragma unroll
        for (int w = 0; w < 4; w++) {
            int h = h0 + w;
            g_bias[((size_t)h * NTOK + i) * NTOK + j0 + r] =
                rv * (acc[u][w] - mu * Ssh[h]) + Bcsh[h];
        }
    }
}

// ===========================================================================
// Kernel 4: flash attention with bias + gating.
// Block = (64-query tile, 1 head). 256 threads: tx 0..15, ty 0..15.
// Score loop d-unrolled by 4 (float4 q). PV loop j-unrolled by 4 (float4 p).
// ===========================================================================
__global__ __launch_bounds__(256) void attn_kernel(const float* __restrict__ mask)
{
    int h  = blockIdx.y;
    int qb = blockIdx.x * 64;
    int tid = threadIdx.x;
    int tx = tid & 15, ty = tid >> 4;
    int r0 = ty * 4;

    __shared__ __align__(16) float qs[64][52];
    __shared__ __align__(16) float kv[64 * 52];     // union: ks_t[48][68] / vs[64][52]
    __shared__ __align__(16) float ps[64][68];

    for (int t = tid; t < 64 * 12; t += 256) {
        int r = t / 12, c4 = (t % 12) * 4;
        float4 v = *(const float4*)&g_q[(qb + r) * HD + h * DH + c4];
        *(float4*)&qs[r][c4] = v;
    }

    float mrow[4], lrow[4], o[4][3];
#pragma unroll
    for (int i = 0; i < 4; i++) {
        mrow[i] = -1e30f; lrow[i] = 0.f;
        o[i][0] = o[i][1] = o[i][2] = 0.f;
    }
    float mq[4];
#pragma unroll
    for (int i = 0; i < 4; i++) mq[i] = mask[qb + r0 + i];

    for (int jt = 0; jt < 16; jt++) {
        int j0 = jt * 64;
        __syncthreads();                      // prev-iter v reads done
        // K transposed: ks_t[d][j], stride 68
        for (int t = tid; t < 64 * 12; t += 256) {
            int j = t & 63, d4 = (t >> 6) * 4;
            float4 v = *(const float4*)&g_k[(j0 + j) * HD + h * DH + d4];
            kv[(d4 + 0) * 68 + j] = v.x;
            kv[(d4 + 1) * 68 + j] = v.y;
            kv[(d4 + 2) * 68 + j] = v.z;
            kv[(d4 + 3) * 68 + j] = v.w;
        }
        __syncthreads();

        float s[4][4];
#pragma unroll
        for (int i = 0; i < 4; i++)
#pragma unroll
            for (int u = 0; u < 4; u++) s[i][u] = 0.f;

        for (int d = 0; d < DH; d += 4) {
            float qa[4][4];
#pragma unroll
            for (int i = 0; i < 4; i++)
                *(float4*)qa[i] = *(const float4*)&qs[r0 + i][d];
#pragma unroll
            for (int dd = 0; dd < 4; dd++) {
                float4 b4 = *(const float4*)&kv[(d + dd) * 68 + tx * 4];
#pragma unroll
                for (int i = 0; i < 4; i++) {
                    float a = qa[i][dd];
                    s[i][0] = fmaf(a, b4.x, s[i][0]);
                    s[i][1] = fmaf(a, b4.y, s[i][1]);
                    s[i][2] = fmaf(a, b4.z, s[i][2]);
                    s[i][3] = fmaf(a, b4.w, s[i][3]);
                }
            }
        }
        float mk[4];
#pragma unroll
        for (int u = 0; u < 4; u++) mk[u] = mask[j0 + tx * 4 + u];
#pragma unroll
        for (int i = 0; i < 4; i++) {
            const float* bp = g_bias + ((size_t)h * NTOK + qb + r0 + i) * NTOK + j0 + tx * 4;
            float4 b4 = *(const float4*)bp;
            s[i][0] += b4.x + INFV * (mq[i] * mk[0] - 1.f);
            s[i][1] += b4.y + INFV * (mq[i] * mk[1] - 1.f);
            s[i][2] += b4.z + INFV * (mq[i] * mk[2] - 1.f);
            s[i][3] += b4.w + INFV * (mq[i] * mk[3] - 1.f);
        }
        // online softmax; row state replicated across the 16 tx lanes
#pragma unroll
        for (int i = 0; i < 4; i++) {
            float mx = fmaxf(fmaxf(s[i][0], s[i][1]), fmaxf(s[i][2], s[i][3]));
#pragma unroll
            for (int off = 1; off < 16; off <<= 1)
                mx = fmaxf(mx, __shfl_xor_sync(0xffffffffu, mx, off));
            float mnew = fmaxf(mrow[i], mx);
            float scale = __expf(mrow[i] - mnew);
            float psum = 0.f;
#pragma unroll
            for (int u = 0; u < 4; u++) { s[i][u] = __expf(s[i][u] - mnew); psum += s[i][u]; }
#pragma unroll
            for (int off = 1; off < 16; off <<= 1)
                psum += __shfl_xor_sync(0xffffffffu, psum, off);
            lrow[i] = lrow[i] * scale + psum;
            mrow[i] = mnew;
            o[i][0] *= scale; o[i][1] *= scale; o[i][2] *= scale;
            *(float4*)&ps[r0 + i][tx * 4] = make_float4(s[i][0], s[i][1], s[i][2], s[i][3]);
        }
        __syncthreads();                      // k reads done, ps visible
        // V natural layout, stride 52
        for (int t = tid; t < 64 * 12; t += 256) {
            int r = t / 12, c4 = (t % 12) * 4;
            float4 v = *(const float4*)&g_v[(j0 + r) * HD + h * DH + c4];
            *(float4*)&kv[r * 52 + c4] = v;
        }
        __syncthreads();
        int d0 = tx * 3;
        for (int j = 0; j < 64; j += 4) {
            float pa[4][4];
#pragma unroll
            for (int i = 0; i < 4; i++)
                *(float4*)pa[i] = *(const float4*)&ps[r0 + i][j];
#pragma unroll
            for (int jj = 0; jj < 4; jj++) {
                int jr = j + jj;
                float b0 = kv[jr * 52 + d0];
                float b1 = kv[jr * 52 + d0 + 1];
                float b2 = kv[jr * 52 + d0 + 2];
#pragma unroll
                for (int i = 0; i < 4; i++) {
                    float p = pa[i][jj];
                    o[i][0] = fmaf(p, b0, o[i][0]);
                    o[i][1] = fmaf(p, b1, o[i][1]);
                    o[i][2] = fmaf(p, b2, o[i][2]);
                }
            }
        }
    }
#pragma unroll
    for (int i = 0; i < 4; i++) {
        int q = qb + r0 + i;
        float inv = 1.f / lrow[i];
        int base = q * HD + h * DH + tx * 3;
#pragma unroll
        for (int u = 0; u < 3; u++)
            g_og[base + u] = o[i][u] * inv * g_g[base + u];
    }
}

// ===========================================================================
// Kernel 5: output projection.  og[1024,768] @ w_o[768,768] + b_o -> out.
// 64x64 tiles -> grid (12,16) = 192 blocks (one full wave on 148 SMs).
// 256 threads, 4x4 microtile.
// ===========================================================================
__global__ __launch_bounds__(256, 4) void outproj_kernel(const float* __restrict__ W,
                                                         const float* __restrict__ bo,
                                                         float* __restrict__ out)
{
    const int BK = 16;
    int n0 = blockIdx.x * 64;
    int m0 = blockIdx.y * 64;

    __shared__ __align__(16) float As[BK][68];
    __shared__ __align__(16) float Bs[BK][64];
    int tid = threadIdx.x;
    int tx = tid & 15, ty = tid >> 4;

    float acc[4][4];
#pragma unroll
    for (int i = 0; i < 4; i++)
#pragma unroll
        for (int j = 0; j < 4; j++) acc[i][j] = 0.f;

    for (int k0 = 0; k0 < HD; k0 += BK) {
        {
            int m = tid >> 2, kq = (tid & 3) * 4;
            float4 av = *(const float4*)&g_og[(m0 + m) * HD + k0 + kq];
            As[kq + 0][m] = av.x; As[kq + 1][m] = av.y;
            As[kq + 2][m] = av.z; As[kq + 3][m] = av.w;
        }
        {
            int r = tid >> 4, c = (tid & 15) * 4;
            *(float4*)&Bs[r][c] = *(const float4*)&W[(k0 + r) * CQ + n0 + c];
        }
        __syncthreads();
#pragma unroll
        for (int k = 0; k < BK; k++) {
            float a[4], b[4];
            *(float4*)a = *(const float4*)&As[k][ty * 4];
            *(float4*)b = *(const float4*)&Bs[k][tx * 4];
#pragma unroll
            for (int i = 0; i < 4; i++)
#pragma unroll
                for (int j = 0; j < 4; j++)
                    acc[i][j] = fmaf(a[i], b[j], acc[i][j]);
        }
        __syncthreads();
    }
#pragma unroll
    for (int i = 0; i < 4; i++) {
        int m = m0 + ty * 4 + i;
        int c = n0 + tx * 4;
        float4 o4;
        o4.x = acc[i][0] + bo[c + 0];
        o4.y = acc[i][1] + bo[c + 1];
        o4.z = acc[i][2] + bo[c + 2];
        o4.w = acc[i][3] + bo[c + 3];
        *(float4*)&out[m * CQ + c] = o4;
    }
}

// ===========================================================================
extern "C" void kernel_launch(void* const* d_in, const int* in_sizes, int n_in,
                              void* d_out, int out_size)
{
    const float* a    = (const float*)d_in[0];
    const float* z    = (const float*)d_in[1];
    const float* mask = (const float*)d_in[2];
    const float* g_a  = (const float*)d_in[3];
    const float* b_a  = (const float*)d_in[4];
    const float* g_z  = (const float*)d_in[5];
    const float* b_z  = (const float*)d_in[6];
    const float* w_z  = (const float*)d_in[7];
    const float* w_q  = (const float*)d_in[8];
    const float* w_k  = (const float*)d_in[9];
    const float* w_v  = (const float*)d_in[10];
    const float* w_g  = (const float*)d_in[11];
    const float* b_g  = (const float*)d_in[12];
    const float* w_o  = (const float*)d_in[13];
    const float* b_o  = (const float*)d_in[14];
    float* out = (float*)d_out;

    ln_a_kernel<<<NTOK, 256>>>(a, g_a, b_a);
    proj_kernel<<<dim3(24, 8), 256>>>(w_q, w_k, w_v, w_g, b_g);
    pairbias_kernel<<<dim3(16, NTOK), 64>>>(z, g_z, b_z, w_z);
    attn_kernel<<<dim3(16, NH), 256>>>(mask);
    outproj_kernel<<<dim3(12, 16), 256>>>(w_o, b_o, out);
}